// round 10
// baseline (speedup 1.0000x reference)
#include <cuda_runtime.h>

#define NPT   16384
#define FDIM  16
#define ATTD  32
#define KNN   32
#define NB    8
#define CDIM  83          // 35 (pe) + 48 (feat)
#define SD    84          // padded row stride (pad element = 0)
#define SD4   21          // SD/4 float4s per row
#define CHUNK 128
#define NCH   (NPT/CHUNK) // 128
#define TI    128
#define TJ    128

// ---- scratch (static device globals; no allocation) ----
__device__ __align__(16) float g_z[NPT * SD];       // combined, then normalized z
__device__ float g_sq[NPT];                          // ||z||^2 per row
__device__ float g_part[NCH][NB][CDIM][2];           // per-chunk partial (sum, sumsq)
__device__ float g_mean[NB][CDIM];
__device__ float g_stdp[NB][CDIM];                   // std + 1e-8
__device__ int   g_ss[NB];
__device__ int   g_se[NB];

// ---------------- K0: segment boundaries (batch is sorted) ----------------
__global__ void k_seg(const int* __restrict__ batch) {
    int tid = threadIdx.x;
    if (tid < NB) { g_ss[tid] = 0; g_se[tid] = 0; }
    __syncthreads();
    for (int n = tid; n < NPT; n += blockDim.x) {
        int b = batch[n];
        if (n == 0 || batch[n - 1] != b) g_ss[b] = n;
        if (n == NPT - 1 || batch[n + 1] != b) g_se[b] = n + 1;
    }
}

// ---------------- K1: enc + MLPs + softmax + combined ----------------
__global__ __launch_bounds__(128) void k_mlp(
    const float* __restrict__ x,   const float* __restrict__ pos,
    const float* __restrict__ w1f, const float* __restrict__ b1f,
    const float* __restrict__ w2f, const float* __restrict__ b2f,
    const float* __restrict__ w1p, const float* __restrict__ b1p,
    const float* __restrict__ w2p, const float* __restrict__ b2p)
{
    __shared__ float s_w1f[48 * 32];
    __shared__ float s_w1p[35 * 32];
    __shared__ float s_b1f[32], s_w2f[32], s_b1p[32], s_w2p[32];
    __shared__ float s_b2f, s_b2p;
    int tid = threadIdx.x;
    for (int i = tid; i < 48 * 32; i += 128) s_w1f[i] = w1f[i];
    for (int i = tid; i < 35 * 32; i += 128) s_w1p[i] = w1p[i];
    if (tid < 32) {
        s_b1f[tid] = b1f[tid]; s_w2f[tid] = w2f[tid];
        s_b1p[tid] = b1p[tid]; s_w2p[tid] = w2p[tid];
    }
    if (tid == 0) { s_b2f = b2f[0]; s_b2p = b2p[0]; }
    __syncthreads();

    int r = blockIdx.x * 128 + tid;
    float p0 = pos[r * 3 + 0];
    float p1 = pos[r * 3 + 1];
    float p2 = pos[r * 3 + 2];

    float feat[48];
#pragma unroll
    for (int i = 0; i < 16; i++) feat[i] = x[r * 16 + i];
    // positional encoding: first 32 channels = sin/cos interleaved of coord0,
    // freqs fb[k] = 1 + k*(9/63), k = 0..15
#pragma unroll
    for (int k = 0; k < 16; k++) {
        float fb = 1.0f + (float)k * (9.0f / 63.0f);
        float s, c;
        sincosf(p0 * fb, &s, &c);
        feat[16 + 2 * k] = s;
        feat[17 + 2 * k] = c;
    }

    // fw = relu(feat @ w1f + b1f) @ w2f + b2f
    float fw = s_b2f;
#pragma unroll 4
    for (int j = 0; j < 32; j++) {
        float h = s_b1f[j];
#pragma unroll
        for (int i = 0; i < 48; i++) h = fmaf(feat[i], s_w1f[i * 32 + j], h);
        h = fmaxf(h, 0.0f);
        fw = fmaf(h, s_w2f[j], fw);
    }
    // pw = relu(pe @ w1p + b1p) @ w2p + b2p ; pe = [xyz, enc]
    float pw = s_b2p;
#pragma unroll 4
    for (int j = 0; j < 32; j++) {
        float h = s_b1p[j];
        h = fmaf(p0, s_w1p[0 * 32 + j], h);
        h = fmaf(p1, s_w1p[1 * 32 + j], h);
        h = fmaf(p2, s_w1p[2 * 32 + j], h);
#pragma unroll
        for (int i = 0; i < 32; i++) h = fmaf(feat[16 + i], s_w1p[(3 + i) * 32 + j], h);
        h = fmaxf(h, 0.0f);
        pw = fmaf(h, s_w2p[j], pw);
    }

    float m  = fmaxf(fw, pw);
    float ef = expf(fw - m), ep = expf(pw - m);
    float inv = 1.0f / (ef + ep);
    float sw0 = ef * inv;   // scales feat
    float sw1 = ep * inv;   // scales pe

    float* zr = &g_z[r * SD];
    zr[0] = p0 * sw1; zr[1] = p1 * sw1; zr[2] = p2 * sw1;
#pragma unroll
    for (int i = 0; i < 32; i++) zr[3 + i]  = feat[16 + i] * sw1;
#pragma unroll
    for (int i = 0; i < 48; i++) zr[35 + i] = feat[i] * sw0;
    zr[83] = 0.0f; // pad
}

// ---------------- K1b: per-chunk partial sums (deterministic) ----------------
__global__ void k_psum(const int* __restrict__ batch) {
    __shared__ float sbin[NB][CDIM][2];
    int d = threadIdx.x;
    if (d < CDIM) {
#pragma unroll
        for (int b = 0; b < NB; b++) { sbin[b][d][0] = 0.0f; sbin[b][d][1] = 0.0f; }
    }
    __syncthreads();
    if (d < CDIM) {
        int base = blockIdx.x * CHUNK;
        int cur = batch[base];
        float s = 0.0f, q = 0.0f;
        for (int r = 0; r < CHUNK; r++) {
            int b = batch[base + r];
            if (b != cur) {
                sbin[cur][d][0] += s; sbin[cur][d][1] += q;
                s = 0.0f; q = 0.0f; cur = b;
            }
            float v = g_z[(base + r) * SD + d];
            s += v;
            q = fmaf(v, v, q);
        }
        sbin[cur][d][0] += s; sbin[cur][d][1] += q;
#pragma unroll
        for (int b = 0; b < NB; b++) {
            g_part[blockIdx.x][b][d][0] = sbin[b][d][0];
            g_part[blockIdx.x][b][d][1] = sbin[b][d][1];
        }
    }
}

// ---------------- K2: mean / std per (batch, dim) ----------------
__global__ void k_stats() {
    int tid = threadIdx.x;
    if (tid >= NB * CDIM) return;
    int b = tid / CDIM, d = tid % CDIM;
    float s = 0.0f, q = 0.0f;
    for (int p = 0; p < NCH; p++) {
        s += g_part[p][b][d][0];
        q += g_part[p][b][d][1];
    }
    float cnt  = (float)(g_se[b] - g_ss[b]);
    float mean = s / fmaxf(cnt, 1.0f);
    float var  = (q - cnt * mean * mean) / fmaxf(cnt - 1.0f, 1.0f);
    float stdv = sqrtf(fmaxf(var, 0.0f));
    g_mean[b][d] = mean;
    g_stdp[b][d] = stdv + 1e-8f;
}

// ---------------- K3: normalize in place + per-row ||z||^2 (warp per row) ----------------
__global__ void k_norm(const int* __restrict__ batch) {
    int warp = (blockIdx.x * blockDim.x + threadIdx.x) >> 5;
    int lane = threadIdx.x & 31;
    if (warp >= NPT) return;
    int b = batch[warp];
    float acc = 0.0f;
#pragma unroll
    for (int t = 0; t < 3; t++) {
        int d = lane + t * 32;
        if (d < CDIM) {
            float z = (g_z[warp * SD + d] - g_mean[b][d]) / g_stdp[b][d];
            g_z[warp * SD + d] = z;
            acc = fmaf(z, z, acc);
        } else if (d == 83) {
            g_z[warp * SD + 83] = 0.0f;
        }
    }
#pragma unroll
    for (int o = 16; o > 0; o >>= 1) acc += __shfl_xor_sync(0xffffffffu, acc, o);
    if (lane == 0) g_sq[warp] = acc;
}

// ---------------- K4: segment-restricted KNN, top-32 per row ----------------
__global__ __launch_bounds__(TI, 2) void k_knn(const int* __restrict__ batch,
                                               float* __restrict__ out) {
    __shared__ float4 tile[TJ * SD4];
    __shared__ float  ssq[TJ];
    int tid = threadIdx.x;
    int r = blockIdx.x * TI + tid;
    int b = batch[r];
    int s = g_ss[b], e = g_se[b];

    // block candidate range = union of segments touched by this row tile
    int b0 = batch[blockIdx.x * TI];
    int b1 = batch[blockIdx.x * TI + TI - 1];
    int rs = g_ss[b0], re = g_se[b1];

    float4 zi[SD4];
    const float4* zrow = (const float4*)&g_z[r * SD];
#pragma unroll
    for (int q = 0; q < SD4; q++) zi[q] = zrow[q];
    float sqi = g_sq[r];

    unsigned long long lst[KNN];
#pragma unroll
    for (int k = 0; k < KNN; k++) lst[k] = 0xFFFFFFFFFFFFFFFFull;

    for (int c0 = rs; c0 < re; c0 += TJ) {
        int m = min(TJ, re - c0);
        __syncthreads();
        for (int idx = tid; idx < m * SD4; idx += TI) {
            int jr = idx / SD4, q = idx % SD4;
            tile[jr * SD4 + q] = ((const float4*)&g_z[(c0 + jr) * SD])[q];
        }
        for (int idx = tid; idx < m; idx += TI) ssq[idx] = g_sq[c0 + idx];
        __syncthreads();

        for (int j = 0; j < m; j++) {
            const float4* zj = &tile[j * SD4];
            float a0 = 0.0f, a1 = 0.0f, a2 = 0.0f, a3 = 0.0f;
#pragma unroll
            for (int q = 0; q < SD4; q++) {
                float4 v = zj[q];
                a0 = fmaf(zi[q].x, v.x, a0);
                a1 = fmaf(zi[q].y, v.y, a1);
                a2 = fmaf(zi[q].z, v.z, a2);
                a3 = fmaf(zi[q].w, v.w, a3);
            }
            float dot = (a0 + a1) + (a2 + a3);
            int g = c0 + j;
            float d2 = fmaf(-2.0f, dot, sqi + ssq[j]);
            unsigned u = __float_as_uint(d2);
            u ^= (u & 0x80000000u) ? 0xFFFFFFFFu : 0x80000000u; // order-preserving
            unsigned long long key = (((unsigned long long)u) << 32) | (unsigned)g;
            if (g >= s && g < e && key < lst[KNN - 1]) {
                lst[KNN - 1] = key;
#pragma unroll
                for (int k = KNN - 1; k > 0; k--) {
                    unsigned long long lo = lst[k - 1], hi = lst[k];
                    bool sw = hi < lo;
                    lst[k - 1] = sw ? hi : lo;
                    lst[k]     = sw ? lo : hi;
                }
            }
        }
    }

    // output (float32): row block [0, N*K), then col block [N*K, 2*N*K)
    float* orow = out;
    float* ocol = out + NPT * KNN;
#pragma unroll
    for (int k = 0; k < KNN; k++) {
        orow[r * KNN + k] = (float)r;
        ocol[r * KNN + k] = (float)(int)(unsigned)(lst[k] & 0xFFFFFFFFull);
    }
}

// ---------------- host ----------------
extern "C" void kernel_launch(void* const* d_in, const int* in_sizes, int n_in,
                              void* d_out, int out_size) {
    const float* x     = (const float*)d_in[0];
    const float* pos   = (const float*)d_in[1];
    const int*   batch = (const int*)d_in[2];
    const float* w1f = (const float*)d_in[3];
    const float* b1f = (const float*)d_in[4];
    const float* w2f = (const float*)d_in[5];
    const float* b2f = (const float*)d_in[6];
    const float* w1p = (const float*)d_in[7];
    const float* b1p = (const float*)d_in[8];
    const float* w2p = (const float*)d_in[9];
    const float* b2p = (const float*)d_in[10];
    float* out = (float*)d_out;

    k_seg<<<1, 1024>>>(batch);
    k_mlp<<<NPT / 128, 128>>>(x, pos, w1f, b1f, w2f, b2f, w1p, b1p, w2p, b2p);
    k_psum<<<NCH, 96>>>(batch);
    k_stats<<<1, 672>>>();
    k_norm<<<NPT / 8, 256>>>(batch);
    k_knn<<<NPT / TI, TI>>>(batch, out);
}

// round 12
// speedup vs baseline: 2.3271x; 2.3271x over previous
#include <cuda_runtime.h>

#define NPT   16384
#define KNN   32
#define NB    8
#define CDIM  83
#define SD    84          // row stride floats (pad = 0)
#define SD4   21          // float4s per row (odd -> conflict-free strided LDS.128)
#define CHUNK 128
#define NCH   (NPT/CHUNK)
#define TJ    128         // candidate tile
#define RPB   16          // rows (warps) per block
#define THR   (RPB*32)

__device__ __align__(16) float g_z[NPT * SD];
__device__ float g_sq[NPT];
__device__ float g_part[NCH][NB][CDIM][2];
__device__ float g_mean[NB][CDIM];
__device__ float g_stdp[NB][CDIM];
__device__ int   g_ss[NB];
__device__ int   g_se[NB];

// ---------------- K0: segment boundaries ----------------
__global__ void k_seg(const int* __restrict__ batch) {
    int tid = threadIdx.x;
    if (tid < NB) { g_ss[tid] = 0; g_se[tid] = 0; }
    __syncthreads();
    for (int n = tid; n < NPT; n += blockDim.x) {
        int b = batch[n];
        if (n == 0 || batch[n - 1] != b) g_ss[b] = n;
        if (n == NPT - 1 || batch[n + 1] != b) g_se[b] = n + 1;
    }
}

// ---------------- K1: enc + MLPs + softmax + combined ----------------
__global__ __launch_bounds__(128) void k_mlp(
    const float* __restrict__ x,   const float* __restrict__ pos,
    const float* __restrict__ w1f, const float* __restrict__ b1f,
    const float* __restrict__ w2f, const float* __restrict__ b2f,
    const float* __restrict__ w1p, const float* __restrict__ b1p,
    const float* __restrict__ w2p, const float* __restrict__ b2p)
{
    __shared__ float s_w1f[48 * 32];
    __shared__ float s_w1p[35 * 32];
    __shared__ float s_b1f[32], s_w2f[32], s_b1p[32], s_w2p[32];
    __shared__ float s_b2f, s_b2p;
    int tid = threadIdx.x;
    for (int i = tid; i < 48 * 32; i += 128) s_w1f[i] = w1f[i];
    for (int i = tid; i < 35 * 32; i += 128) s_w1p[i] = w1p[i];
    if (tid < 32) {
        s_b1f[tid] = b1f[tid]; s_w2f[tid] = w2f[tid];
        s_b1p[tid] = b1p[tid]; s_w2p[tid] = w2p[tid];
    }
    if (tid == 0) { s_b2f = b2f[0]; s_b2p = b2p[0]; }
    __syncthreads();

    int r = blockIdx.x * 128 + tid;
    float p0 = pos[r * 3 + 0];
    float p1 = pos[r * 3 + 1];
    float p2 = pos[r * 3 + 2];

    float feat[48];
#pragma unroll
    for (int i = 0; i < 16; i++) feat[i] = x[r * 16 + i];
#pragma unroll
    for (int k = 0; k < 16; k++) {
        float fb = 1.0f + (float)k * (9.0f / 63.0f);
        float s, c;
        sincosf(p0 * fb, &s, &c);
        feat[16 + 2 * k] = s;
        feat[17 + 2 * k] = c;
    }

    float fw = s_b2f;
#pragma unroll 4
    for (int j = 0; j < 32; j++) {
        float h = s_b1f[j];
#pragma unroll
        for (int i = 0; i < 48; i++) h = fmaf(feat[i], s_w1f[i * 32 + j], h);
        h = fmaxf(h, 0.0f);
        fw = fmaf(h, s_w2f[j], fw);
    }
    float pw = s_b2p;
#pragma unroll 4
    for (int j = 0; j < 32; j++) {
        float h = s_b1p[j];
        h = fmaf(p0, s_w1p[0 * 32 + j], h);
        h = fmaf(p1, s_w1p[1 * 32 + j], h);
        h = fmaf(p2, s_w1p[2 * 32 + j], h);
#pragma unroll
        for (int i = 0; i < 32; i++) h = fmaf(feat[16 + i], s_w1p[(3 + i) * 32 + j], h);
        h = fmaxf(h, 0.0f);
        pw = fmaf(h, s_w2p[j], pw);
    }

    float m  = fmaxf(fw, pw);
    float ef = expf(fw - m), ep = expf(pw - m);
    float inv = 1.0f / (ef + ep);
    float sw0 = ef * inv;
    float sw1 = ep * inv;

    float* zr = &g_z[r * SD];
    zr[0] = p0 * sw1; zr[1] = p1 * sw1; zr[2] = p2 * sw1;
#pragma unroll
    for (int i = 0; i < 32; i++) zr[3 + i]  = feat[16 + i] * sw1;
#pragma unroll
    for (int i = 0; i < 48; i++) zr[35 + i] = feat[i] * sw0;
    zr[83] = 0.0f;
}

// ---------------- K1b: per-chunk partial sums ----------------
__global__ void k_psum(const int* __restrict__ batch) {
    __shared__ float sbin[NB][CDIM][2];
    int d = threadIdx.x;
    if (d < CDIM) {
#pragma unroll
        for (int b = 0; b < NB; b++) { sbin[b][d][0] = 0.0f; sbin[b][d][1] = 0.0f; }
    }
    __syncthreads();
    if (d < CDIM) {
        int base = blockIdx.x * CHUNK;
        int cur = batch[base];
        float s = 0.0f, q = 0.0f;
        for (int r = 0; r < CHUNK; r++) {
            int b = batch[base + r];
            if (b != cur) {
                sbin[cur][d][0] += s; sbin[cur][d][1] += q;
                s = 0.0f; q = 0.0f; cur = b;
            }
            float v = g_z[(base + r) * SD + d];
            s += v;
            q = fmaf(v, v, q);
        }
        sbin[cur][d][0] += s; sbin[cur][d][1] += q;
#pragma unroll
        for (int b = 0; b < NB; b++) {
            g_part[blockIdx.x][b][d][0] = sbin[b][d][0];
            g_part[blockIdx.x][b][d][1] = sbin[b][d][1];
        }
    }
}

// ---------------- K2: stats ----------------
__global__ void k_stats() {
    int tid = threadIdx.x;
    if (tid >= NB * CDIM) return;
    int b = tid / CDIM, d = tid % CDIM;
    float s = 0.0f, q = 0.0f;
    for (int p = 0; p < NCH; p++) {
        s += g_part[p][b][d][0];
        q += g_part[p][b][d][1];
    }
    float cnt  = (float)(g_se[b] - g_ss[b]);
    float mean = s / fmaxf(cnt, 1.0f);
    float var  = (q - cnt * mean * mean) / fmaxf(cnt - 1.0f, 1.0f);
    float stdv = sqrtf(fmaxf(var, 0.0f));
    g_mean[b][d] = mean;
    g_stdp[b][d] = stdv + 1e-8f;
}

// ---------------- K3: normalize + ||z||^2 ----------------
__global__ void k_norm(const int* __restrict__ batch) {
    int warp = (blockIdx.x * blockDim.x + threadIdx.x) >> 5;
    int lane = threadIdx.x & 31;
    if (warp >= NPT) return;
    int b = batch[warp];
    float acc = 0.0f;
#pragma unroll
    for (int t = 0; t < 3; t++) {
        int d = lane + t * 32;
        if (d < CDIM) {
            float z = (g_z[warp * SD + d] - g_mean[b][d]) / g_stdp[b][d];
            g_z[warp * SD + d] = z;
            acc = fmaf(z, z, acc);
        } else if (d == 83) {
            g_z[warp * SD + 83] = 0.0f;
        }
    }
#pragma unroll
    for (int o = 16; o > 0; o >>= 1) acc += __shfl_xor_sync(0xffffffffu, acc, o);
    if (lane == 0) g_sq[warp] = acc;
}

// ---------------- shfl helpers (u64) ----------------
__device__ __forceinline__ unsigned long long shflx64(unsigned long long v, int m) {
    unsigned lo = (unsigned)v, hi = (unsigned)(v >> 32);
    lo = __shfl_xor_sync(0xffffffffu, lo, m);
    hi = __shfl_xor_sync(0xffffffffu, hi, m);
    return ((unsigned long long)hi << 32) | lo;
}
__device__ __forceinline__ unsigned long long shfl64(unsigned long long v, int src) {
    unsigned lo = (unsigned)v, hi = (unsigned)(v >> 32);
    lo = __shfl_sync(0xffffffffu, lo, src);
    hi = __shfl_sync(0xffffffffu, hi, src);
    return ((unsigned long long)hi << 32) | lo;
}

// ---------------- K4: warp-per-row KNN, distributed bitonic top-32 ----------------
__global__ __launch_bounds__(THR, 1) void k_knn(const int* __restrict__ batch,
                                                float* __restrict__ out) {
    __shared__ float4 tile[TJ * SD4];   // 43 KB
    __shared__ float  ssq[TJ];
    int tid  = threadIdx.x;
    int wid  = tid >> 5;
    int lane = tid & 31;
    int r = blockIdx.x * RPB + wid;     // this warp's row
    int b = batch[r];
    int s = g_ss[b], e = g_se[b];

    int b0 = batch[blockIdx.x * RPB];
    int b1 = batch[blockIdx.x * RPB + RPB - 1];
    int rs = g_ss[b0], re = g_se[b1];

    // every lane holds the full query row (identical arithmetic to prev round)
    float4 zi[SD4];
    const float4* zrow = (const float4*)&g_z[r * SD];
#pragma unroll
    for (int q = 0; q < SD4; q++) zi[q] = zrow[q];
    float sqi = g_sq[r];

    // distributed sorted top-32: lane k holds k-th smallest key
    unsigned long long L = 0xFFFFFFFFFFFFFFFFull;
    unsigned long long Lmax = 0xFFFFFFFFFFFFFFFFull;

    for (int c0 = rs; c0 < re; c0 += TJ) {
        int m = min(TJ, re - c0);
        __syncthreads();
        // flat float4 copy (g_z rows are contiguous, SD=84 floats = 21 float4)
        const float4* src = (const float4*)&g_z[c0 * SD];
        for (int i = tid; i < m * SD4; i += THR) tile[i] = src[i];
        for (int i = tid; i < m; i += THR) ssq[i] = g_sq[c0 + i];
        __syncthreads();

        for (int jb = 0; jb < m; jb += 32) {
            int j = jb + lane;
            // dot(z_r, z_j): same 4-accumulator float4 fma chain as before
            const float4* zj = &tile[j * SD4];   // j < TJ always (stale data ok; masked below)
            float a0 = 0.0f, a1 = 0.0f, a2 = 0.0f, a3 = 0.0f;
#pragma unroll
            for (int q = 0; q < SD4; q++) {
                float4 v = zj[q];
                a0 = fmaf(zi[q].x, v.x, a0);
                a1 = fmaf(zi[q].y, v.y, a1);
                a2 = fmaf(zi[q].z, v.z, a2);
                a3 = fmaf(zi[q].w, v.w, a3);
            }
            float dot = (a0 + a1) + (a2 + a3);
            int g = c0 + j;
            float d2 = fmaf(-2.0f, dot, sqi + ssq[j]);
            unsigned u = __float_as_uint(d2);
            u ^= (u & 0x80000000u) ? 0xFFFFFFFFu : 0x80000000u;
            unsigned long long nkey = (((unsigned long long)u) << 32) | (unsigned)g;
            if (j >= m || g < s || g >= e) nkey = 0xFFFFFFFFFFFFFFFFull;

            if (__any_sync(0xffffffffu, nkey < Lmax)) {
                // bitonic sort the 32 new keys ascending across lanes
#pragma unroll
                for (int k = 2; k <= 32; k <<= 1) {
#pragma unroll
                    for (int jj = k >> 1; jj > 0; jj >>= 1) {
                        unsigned long long o = shflx64(nkey, jj);
                        bool takemin = ((lane & k) == 0) == ((lane & jj) == 0);
                        nkey = (takemin == (nkey < o)) ? nkey : o;
                    }
                }
                // merge: keep 32 smallest of (L asc, nkey asc)
                unsigned long long rev = shflx64(nkey, 31);       // reversed new list
                unsigned long long Lm = (L < rev) ? L : rev;      // bitonic
#pragma unroll
                for (int jj = 16; jj > 0; jj >>= 1) {
                    unsigned long long o = shflx64(Lm, jj);
                    bool takemin = (lane & jj) == 0;
                    Lm = (takemin == (Lm < o)) ? Lm : o;
                }
                L = Lm;
                Lmax = shfl64(L, 31);
            }
        }
    }

    // output (float32): row block [0, N*K), col block [N*K, 2*N*K); lane k -> slot k
    out[r * KNN + lane]             = (float)r;
    out[NPT * KNN + r * KNN + lane] = (float)(int)(unsigned)(L & 0xFFFFFFFFull);
}

// ---------------- host ----------------
extern "C" void kernel_launch(void* const* d_in, const int* in_sizes, int n_in,
                              void* d_out, int out_size) {
    const float* x     = (const float*)d_in[0];
    const float* pos   = (const float*)d_in[1];
    const int*   batch = (const int*)d_in[2];
    const float* w1f = (const float*)d_in[3];
    const float* b1f = (const float*)d_in[4];
    const float* w2f = (const float*)d_in[5];
    const float* b2f = (const float*)d_in[6];
    const float* w1p = (const float*)d_in[7];
    const float* b1p = (const float*)d_in[8];
    const float* w2p = (const float*)d_in[9];
    const float* b2p = (const float*)d_in[10];
    float* out = (float*)d_out;

    k_seg<<<1, 1024>>>(batch);
    k_mlp<<<NPT / 128, 128>>>(x, pos, w1f, b1f, w2f, b2f, w1p, b1p, w2p, b2p);
    k_psum<<<NCH, 96>>>(batch);
    k_stats<<<1, 672>>>();
    k_norm<<<NPT / 8, 256>>>(batch);
    k_knn<<<NPT / RPB, THR>>>(batch, out);
}